// round 5
// baseline (speedup 1.0000x reference)
#include <cuda_runtime.h>
#include <math.h>

#define BB 4
#define DD 64
#define NV (DD*DD*DD)        // 262144 voxels per batch (2^18)
#define TOT (BB*NV)          // 1048576
#define NP 512               // points per batch
#define NCOL (TOT/64)        // 16384 z-columns

// -------- scratch (device globals: no allocations allowed) --------
__device__ double g_part[256];
__device__ float  g_mean;
__device__ int    g_parent[TOT];                 // -1 = background
__device__ unsigned long long g_colmask[NCOL];   // foreground bits per z-column
__device__ int    g_num[BB];                     // component count per batch

// -------- 1) deterministic mean: two fixed-order tree reductions ----------
__global__ void k_reduce1(const float* __restrict__ x) {
    __shared__ double sh[256];
    const int t = threadIdx.x, bk = blockIdx.x;
    const int CH4 = (TOT / 256) / 4;       // 1024 float4 per block
    const float4* __restrict__ x4 = (const float4*)x + bk * CH4;
    double s = 0.0;
    for (int i = t; i < CH4; i += 256) {
        float4 v = x4[i];
        s += ((double)v.x + (double)v.y) + ((double)v.z + (double)v.w);
    }
    sh[t] = s; __syncthreads();
    for (int o = 128; o > 0; o >>= 1) { if (t < o) sh[t] += sh[t + o]; __syncthreads(); }
    if (t == 0) g_part[bk] = sh[0];
}

__global__ void k_reduce2() {
    __shared__ double sh[256];
    const int t = threadIdx.x;
    sh[t] = g_part[t]; __syncthreads();
    for (int o = 128; o > 0; o >>= 1) { if (t < o) sh[t] += sh[t + o]; __syncthreads(); }
    if (t == 0) g_mean = (float)(sh[0] / (double)TOT);
    if (t < BB) g_num[t] = 0;              // re-zero every replay
}

// -------- 2) init: z-run-start labels + column masks + run counts ----------
// block = 256 threads = 4 columns x 64 z
__global__ void k_init(const float* __restrict__ x) {
    __shared__ unsigned int shm[8];        // 8 half-column ballots
    const int t = threadIdx.x;
    const int z = t & 63;
    const int col = blockIdx.x * 4 + (t >> 6);
    const int i = (col << 6) + z;

    const bool fg = (x[i] > g_mean);
    const unsigned int b32 = __ballot_sync(0xFFFFFFFFu, fg);
    if ((t & 31) == 0) shm[t >> 5] = b32;
    __syncthreads();

    const int c = t >> 6;
    const unsigned long long m =
        (unsigned long long)shm[c * 2] |
        ((unsigned long long)shm[c * 2 + 1] << 32);

    if (fg) {
        const unsigned long long below =
            (z == 0) ? 0ull : (~m & ((1ull << z) - 1ull));
        const int start = below ? (64 - __clzll(below)) : 0;
        g_parent[i] = (col << 6) + start;
    } else {
        g_parent[i] = -1;
    }

    if (z == 0) {
        g_colmask[col] = m;
        const unsigned long long starts = m & ~(m << 1);
        const int nruns = __popcll(starts);
        if (nruns) atomicAdd(&g_num[col >> 12], nruns);
    }
}

// -------- ECL-CC style union-find ----------
// find with path compression via benign plain stores (Jaiganesh & Burtscher).
// Values along a chain strictly decrease; a written value is always a valid
// ancestor, so concurrent races stay correct.
__device__ __forceinline__ int uf_find(int v) {
    volatile int* L = g_parent;
    int cur = L[v];
    if (cur == v) return v;
    int prev = v, next;
    while (cur > (next = L[cur])) {
        L[prev] = next;                    // compress (benign race)
        prev = cur;
        cur = next;
    }
    return cur;
}

// read-only find (post-merge phases)
__device__ __forceinline__ int uf_find_ro(int v) {
    volatile int* L = g_parent;
    int cur = L[v];
    while (true) {
        const int next = L[cur];
        if (next == cur) return cur;
        cur = next;
    }
}

// hook larger root under smaller via CAS; decrement count exactly once per
// successful demotion (a root can only be demoted once, ever).
__device__ __forceinline__ void uf_unite(int a, int b) {
    int ra = uf_find(a);
    int rb = uf_find(b);
    while (ra != rb) {
        if (ra < rb) { const int t = ra; ra = rb; rb = t; }   // ra > rb
        const int old = atomicCAS(&g_parent[ra], ra, rb);
        if (old == ra) {
            atomicSub(&g_num[ra >> 18], 1);
            return;
        }
        ra = uf_find(old);
        rb = uf_find(rb);
    }
}

// run start of z-run containing bit z of mask m (bit z must be set)
__device__ __forceinline__ int run_start(unsigned long long m, int z) {
    const unsigned long long below =
        (z == 0) ? 0ull : (~m & ((1ull << z) - 1ull));
    return below ? (64 - __clzll(below)) : 0;
}

// -------- 3) merge: one thread per (voxel, x/y-dir); dedup to run-starts ----
__global__ void k_merge() {
    const int t = blockIdx.x * blockDim.x + threadIdx.x;
    const int i = t & (TOT - 1);
    const int dir = t >> 20;               // 0: -y, 1: -x
    const int z = i & 63;
    const int col = i >> 6;
    const int y = col & 63;
    const int x = (col >> 6) & 63;
    int nbr;
    if (dir == 0) { if (y == 0) return; nbr = col - 1;  }
    else          { if (x == 0) return; nbr = col - 64; }

    const unsigned long long mA = __ldg(&g_colmask[col]);
    const unsigned long long mB = __ldg(&g_colmask[nbr]);
    const unsigned long long ov = mA & mB;
    if (!((ov >> z) & 1ull)) return;                 // no edge at this z
    if (z > 0 && ((ov >> (z - 1)) & 1ull)) return;   // not an overlap-run start

    const int a = (col << 6) + run_start(mA, z);     // z-run roots
    const int b = (nbr << 6) + run_start(mB, z);
    uf_unite(a, b);
}

// -------- 4) fused point lookup + per-batch RMS (O(P^2) in shared) --------
__global__ void k_rms(const float* __restrict__ pts, float* __restrict__ out) {
    __shared__ int sh[NP];
    __shared__ int s_h0, s_sq, s_nc;
    const int b = blockIdx.x, t = threadIdx.x;

    const float* p = pts + (b * NP + t) * 3;
    const int s0 = (int)p[0];              // pts in [0, 64-1e-3): trunc == floor
    const int s1 = (int)p[1];
    const int s2 = (int)p[2];
    const int flat = (b << 18) + (s0 << 12) + (s1 << 6) + s2;
    const int pr = g_parent[flat];
    const int h = (pr >= 0) ? (uf_find_ro(flat) + 1) : 0;

    sh[t] = h;
    if (t == 0) { s_h0 = 0; s_sq = 0; s_nc = 0; }
    __syncthreads();

    int cnt = 0, first = -1;
    #pragma unroll 8
    for (int j = 0; j < NP; j++) {
        if (sh[j] == h) { if (cnt == 0) first = j; cnt++; }
    }
    if (h == 0) {
        atomicAdd(&s_h0, 1);
    } else if (first == t) {               // representative of a hit component
        const int d = cnt - 1;
        atomicAdd(&s_sq, d * d);           // (1-cnt)^2, exact in int
        atomicAdd(&s_nc, 1);
    }
    __syncthreads();
    if (t == 0) {
        const float num = (float)g_num[b];
        const float sq = (float)s_h0 * (float)s_h0
                       + (float)s_sq
                       + (num - (float)s_nc);   // unhit components
        out[b] = sqrtf(sq / (num + 1.0f));
    }
}

// -------- launcher ----------
extern "C" void kernel_launch(void* const* d_in, const int* in_sizes, int n_in,
                              void* d_out, int out_size) {
    const float* logits = (const float*)d_in[0];
    const float* pts    = (const float*)d_in[1];
    if (n_in >= 2 && in_sizes[0] != TOT) {   // defensive input-order check
        logits = (const float*)d_in[1];
        pts    = (const float*)d_in[0];
    }
    k_reduce1<<<256, 256>>>(logits);
    k_reduce2<<<1, 256>>>();
    k_init<<<TOT / 256, 256>>>(logits);
    k_merge<<<(2 * TOT) / 256, 256>>>();
    k_rms<<<BB, NP>>>(pts, (float*)d_out);
}

// round 6
// speedup vs baseline: 3.9408x; 3.9408x over previous
#include <cuda_runtime.h>
#include <math.h>

#define BB 4
#define DD 64
#define NV (DD*DD*DD)        // 262144 voxels per batch (2^18)
#define TOT (BB*NV)          // 1048576
#define NP 512               // points per batch
#define NCOL (TOT/64)        // 16384 z-columns

// -------- scratch (device globals: no allocations allowed) --------
__device__ double g_part[256];
__device__ float  g_mean;
__device__ int    g_parent[TOT];                 // -1 = background
__device__ unsigned long long g_colmask[NCOL];   // foreground bits per z-column
__device__ int    g_num[BB];                     // component count per batch

// -------- 1) deterministic mean: two fixed-order tree reductions ----------
__global__ void k_reduce1(const float* __restrict__ x) {
    __shared__ double sh[256];
    const int t = threadIdx.x, bk = blockIdx.x;
    const int CH4 = (TOT / 256) / 4;       // 1024 float4 per block
    const float4* __restrict__ x4 = (const float4*)x + bk * CH4;
    double s = 0.0;
    for (int i = t; i < CH4; i += 256) {
        float4 v = x4[i];
        s += ((double)v.x + (double)v.y) + ((double)v.z + (double)v.w);
    }
    sh[t] = s; __syncthreads();
    for (int o = 128; o > 0; o >>= 1) { if (t < o) sh[t] += sh[t + o]; __syncthreads(); }
    if (t == 0) g_part[bk] = sh[0];
}

__global__ void k_reduce2() {
    __shared__ double sh[256];
    const int t = threadIdx.x;
    sh[t] = g_part[t]; __syncthreads();
    for (int o = 128; o > 0; o >>= 1) { if (t < o) sh[t] += sh[t + o]; __syncthreads(); }
    if (t == 0) g_mean = (float)(sh[0] / (double)TOT);
    if (t < BB) g_num[t] = 0;              // re-zero every replay
}

// -------- 2) init: z-run-start labels + column masks (no atomics) ----------
// block = 256 threads = 4 columns x 64 z
__global__ void k_init(const float* __restrict__ x) {
    __shared__ unsigned int shm[8];        // 8 half-column ballots
    const int t = threadIdx.x;
    const int z = t & 63;
    const int col = blockIdx.x * 4 + (t >> 6);
    const int i = (col << 6) + z;

    const bool fg = (x[i] > g_mean);
    const unsigned int b32 = __ballot_sync(0xFFFFFFFFu, fg);
    if ((t & 31) == 0) shm[t >> 5] = b32;
    __syncthreads();

    const int c = t >> 6;
    const unsigned long long m =
        (unsigned long long)shm[c * 2] |
        ((unsigned long long)shm[c * 2 + 1] << 32);

    if (fg) {
        const unsigned long long below =
            (z == 0) ? 0ull : (~m & ((1ull << z) - 1ull));
        const int start = below ? (64 - __clzll(below)) : 0;
        g_parent[i] = (col << 6) + start;
    } else {
        g_parent[i] = -1;
    }

    if (z == 0) g_colmask[col] = m;
}

// -------- global union-find: read-only find, min-link union (NO counting) ----
__device__ __forceinline__ int uf_find(int i) {
    int p = g_parent[i];
    while (p != i) { i = p; p = g_parent[i]; }
    return i;
}

__device__ __forceinline__ void uf_unite(int a, int b) {
    while (true) {
        a = uf_find(a);
        b = uf_find(b);
        if (a == b) return;
        if (a > b) { int t = a; a = b; b = t; }
        const int old = atomicMin(&g_parent[b], a);
        if (old == b) return;
        b = old;
    }
}

// run start of z-run containing bit z of mask m (bit z must be set)
__device__ __forceinline__ int run_start(unsigned long long m, int z) {
    const unsigned long long below =
        (z == 0) ? 0ull : (~m & ((1ull << z) - 1ull));
    return below ? (64 - __clzll(below)) : 0;
}

// -------- 3) merge: one thread per (voxel, x/y-dir); dedup to run-starts ----
__global__ void k_merge() {
    const int t = blockIdx.x * blockDim.x + threadIdx.x;
    const int i = t & (TOT - 1);
    const int dir = t >> 20;               // 0: -y, 1: -x
    const int z = i & 63;
    const int col = i >> 6;
    const int y = col & 63;
    const int x = (col >> 6) & 63;
    int nbr;
    if (dir == 0) { if (y == 0) return; nbr = col - 1;  }
    else          { if (x == 0) return; nbr = col - 64; }

    const unsigned long long mA = __ldg(&g_colmask[col]);
    const unsigned long long mB = __ldg(&g_colmask[nbr]);
    const unsigned long long ov = mA & mB;
    if (!((ov >> z) & 1ull)) return;                 // no edge at this z
    if (z > 0 && ((ov >> (z - 1)) & 1ull)) return;   // not an overlap-run start

    const int a = (col << 6) + run_start(mA, z);     // z-run roots
    const int b = (nbr << 6) + run_start(mB, z);
    uf_unite(a, b);
}

// -------- 4) count roots: block-aggregated (one atomic per 256 voxels) -----
__global__ void k_count() {
    const int i = blockIdx.x * blockDim.x + threadIdx.x;
    const int isroot = (g_parent[i] == i) ? 1 : 0;
    const int nblk = __syncthreads_count(isroot);
    if (threadIdx.x == 0 && nblk)
        atomicAdd(&g_num[i >> 18], nblk);  // block spans one batch segment
}

// -------- 5) fused point lookup + per-batch RMS (O(P^2) in shared) --------
__global__ void k_rms(const float* __restrict__ pts, float* __restrict__ out) {
    __shared__ int sh[NP];
    __shared__ int s_h0, s_sq, s_nc;
    const int b = blockIdx.x, t = threadIdx.x;

    const float* p = pts + (b * NP + t) * 3;
    const int s0 = (int)p[0];              // pts in [0, 64-1e-3): trunc == floor
    const int s1 = (int)p[1];
    const int s2 = (int)p[2];
    const int flat = (b << 18) + (s0 << 12) + (s1 << 6) + s2;
    const int pr = g_parent[flat];
    const int h = (pr >= 0) ? (uf_find(flat) + 1) : 0;

    sh[t] = h;
    if (t == 0) { s_h0 = 0; s_sq = 0; s_nc = 0; }
    __syncthreads();

    int cnt = 0, first = -1;
    #pragma unroll 8
    for (int j = 0; j < NP; j++) {
        if (sh[j] == h) { if (cnt == 0) first = j; cnt++; }
    }
    if (h == 0) {
        atomicAdd(&s_h0, 1);
    } else if (first == t) {               // representative of a hit component
        const int d = cnt - 1;
        atomicAdd(&s_sq, d * d);           // (1-cnt)^2, exact in int
        atomicAdd(&s_nc, 1);
    }
    __syncthreads();
    if (t == 0) {
        const float num = (float)g_num[b];
        const float sq = (float)s_h0 * (float)s_h0
                       + (float)s_sq
                       + (num - (float)s_nc);   // unhit components
        out[b] = sqrtf(sq / (num + 1.0f));
    }
}

// -------- launcher ----------
extern "C" void kernel_launch(void* const* d_in, const int* in_sizes, int n_in,
                              void* d_out, int out_size) {
    const float* logits = (const float*)d_in[0];
    const float* pts    = (const float*)d_in[1];
    if (n_in >= 2 && in_sizes[0] != TOT) {   // defensive input-order check
        logits = (const float*)d_in[1];
        pts    = (const float*)d_in[0];
    }
    k_reduce1<<<256, 256>>>(logits);
    k_reduce2<<<1, 256>>>();
    k_init<<<TOT / 256, 256>>>(logits);
    k_merge<<<(2 * TOT) / 256, 256>>>();
    k_count<<<TOT / 256, 256>>>();
    k_rms<<<BB, NP>>>(pts, (float*)d_out);
}